// round 3
// baseline (speedup 1.0000x reference)
#include <cuda_runtime.h>
#include <cuda_bf16.h>

#define BN_ 640
#define TSTEPS 127
#define AA_ 6

// scratch (device global: no allocations allowed)
__device__ float g_state_emb[BN_ * 64];

__device__ __forceinline__ float fsigm(float x) {
    return 1.f / (1.f + expf(-x));
}

// ---------------------------------------------------------------------------
// Encoder: per-row conv1->conv2->fc on frame 0, plus action-mask output.
// grid = 640 blocks (one per row), 128 threads.
// ---------------------------------------------------------------------------
__global__ void __launch_bounds__(128) encoder_kernel(
    const float* __restrict__ s_h, const int* __restrict__ a_h,
    const float* __restrict__ w1, const float* __restrict__ b1,
    const float* __restrict__ w2, const float* __restrict__ b2,
    const float* __restrict__ fcw, const float* __restrict__ fcb,
    float* __restrict__ out_masks)
{
    __shared__ float s0[512];    // 8x8x8 input frame
    __shared__ float o1[1152];   // 32x6x6
    __shared__ float o2[512];    // 32x4x4
    __shared__ float red[128];

    int row = blockIdx.x;
    int t = threadIdx.x;

    for (int i = t; i < 512; i += 128) s0[i] = s_h[row * 65536 + i]; // frame t=0

    // action masks: (a != A-1), T=128 per row
    {
        int v = a_h[row * 128 + t];
        out_masks[row * 128 + t] = (v != (AA_ - 1)) ? 1.f : 0.f;
    }
    __syncthreads();

    // conv1: 8ch 8x8 -> 32ch 6x6
    for (int idx = t; idx < 1152; idx += 128) {
        int oc = idx / 36, rem = idx % 36, y = rem / 6, x = rem % 6;
        float s = b1[oc];
        const float* wp = w1 + oc * 72;
        #pragma unroll
        for (int ic = 0; ic < 8; ic++)
            #pragma unroll
            for (int ky = 0; ky < 3; ky++)
                #pragma unroll
                for (int kx = 0; kx < 3; kx++)
                    s += s0[ic * 64 + (y + ky) * 8 + (x + kx)] * __ldg(wp + ic * 9 + ky * 3 + kx);
        o1[idx] = fmaxf(s, 0.f);
    }
    __syncthreads();

    // conv2: 32ch 6x6 -> 32ch 4x4
    for (int idx = t; idx < 512; idx += 128) {
        int oc = idx >> 4, y = (idx >> 2) & 3, x = idx & 3;
        float s = b2[oc];
        const float* wp = w2 + oc * 288;
        for (int ic = 0; ic < 32; ic++) {
            const float* ip = o1 + ic * 36 + y * 6 + x;
            const float* kp = wp + ic * 9;
            #pragma unroll
            for (int ky = 0; ky < 3; ky++)
                #pragma unroll
                for (int kx = 0; kx < 3; kx++)
                    s += ip[ky * 6 + kx] * __ldg(kp + ky * 3 + kx);
        }
        o2[idx] = fmaxf(s, 0.f);
    }
    __syncthreads();

    // fc: 512 -> 64 (two k-halves per output, then reduce)
    {
        int o = t & 63, half = t >> 6;
        const float* wp = fcw + o * 512 + half * 256;
        const float* xp = o2 + half * 256;
        float s = 0.f;
        for (int k = 0; k < 256; k += 4)
            s += wp[k] * xp[k] + wp[k + 1] * xp[k + 1]
               + wp[k + 2] * xp[k + 2] + wp[k + 3] * xp[k + 3];
        red[t] = s;
    }
    __syncthreads();
    if (t < 64) {
        float v = red[t] + red[t + 64] + fcb[t];
        g_state_emb[row * 64 + t] = fmaxf(v, 0.f);
    }
}

// ---------------------------------------------------------------------------
// Recurrent rollout. grid = 160 blocks x 128 threads, 4 rows per block.
// Lane = r(2 bits) + 4*s(3 bits); warp w owns GRU output dims [16w, 16w+16).
// Weights staged in shared, transposed [k4][o] float4 so each weight LDS.128
// is shared by the 4 rows in a warp.
// ---------------------------------------------------------------------------
__global__ void __launch_bounds__(128) recur_kernel(
    const float* __restrict__ b_z, const float* __restrict__ emb,
    const float* __restrict__ wih, const float* __restrict__ whh,
    const float* __restrict__ bih, const float* __restrict__ bhh_g,
    const float* __restrict__ m1w, const float* __restrict__ m1b,
    const float* __restrict__ m2w, const float* __restrict__ m2b,
    float* __restrict__ out_logits)
{
    extern __shared__ float4 sm4[];
    float4* WQ = sm4;                    // [16][192] Whh^T blocks
    float4* M1 = WQ + 16 * 192;          // [16][64]
    float4* M2 = M1 + 16 * 64;           // [16][8] (o padded to 8)
    float*  AT = (float*)(M2 + 16 * 8);  // [6][208] act table (padded stride)
    float*  HS = AT + 6 * 208;           // [2][4][68] h double buffer (544 floats)
    float*  HD = HS + 2 * 4 * 68;        // [4][68] hid exchange (272 floats)

    int t = threadIdx.x;
    int w = t >> 5, lane = t & 31;
    int r = lane & 3, s = lane >> 2;
    int row = blockIdx.x * 4 + r;

    // ---- stage weights (transposed) ----
    for (int idx = t; idx < 16 * 192; idx += 128) {
        int o = idx >> 4, k4 = idx & 15;
        WQ[k4 * 192 + o] = *(const float4*)(whh + o * 64 + k4 * 4);
    }
    for (int idx = t; idx < 16 * 64; idx += 128) {
        int o = idx >> 4, k4 = idx & 15;
        M1[k4 * 64 + o] = *(const float4*)(m1w + o * 64 + k4 * 4);
    }
    for (int idx = t; idx < 16 * 8; idx += 128) {
        int o = idx >> 4, k4 = idx & 15;
        float4 v = make_float4(0.f, 0.f, 0.f, 0.f);
        if (o < 6) v = *(const float4*)(m2w + o * 64 + k4 * 4);
        M2[k4 * 8 + o] = v;
    }
    // act_table[a][o] = sum_j emb[a][j] * Wih[o][64+j]
    for (int idx = t; idx < 6 * 192; idx += 128) {
        int a = idx / 192, o = idx % 192;
        float sum = 0.f;
        #pragma unroll
        for (int j = 0; j < 6; j++) sum += emb[a * 6 + j] * wih[o * 134 + 64 + j];
        AT[a * 208 + o] = sum;
    }
    // FULL zero-init of both h buffers + hid exchange. (Previous round only
    // zeroed 256/544 floats of HS -> stale smem across graph replays caused
    // the post-timing divergence.)
    for (int i = t; i < 2 * 4 * 68 + 4 * 68; i += 128) HS[i] = 0.f;
    __syncthreads();

    // ---- per-lane constants: base gx (state_emb & b_z parts + bih) ----
    int d0 = w * 16 + s, d1 = d0 + 8;
    int oidx[6];
    oidx[0] = d0;        oidx[1] = d1;         // r-gate
    oidx[2] = 64 + d0;   oidx[3] = 64 + d1;    // z-gate
    oidx[4] = 128 + d0;  oidx[5] = 128 + d1;   // n-gate

    float bgx[6], bhhr[6];
    {
        const float* se = g_state_emb + row * 64;
        const float* bz = b_z + (row / 10) * 64;
        #pragma unroll
        for (int j = 0; j < 6; j++) {
            int o = oidx[j];
            const float* wr = wih + o * 134;
            float sum = bih[o];
            for (int k = 0; k < 64; k++) sum += se[k] * wr[k];
            for (int k = 0; k < 64; k++) sum += bz[k] * wr[70 + k];
            bgx[j] = sum;
            bhhr[j] = bhh_g[o];
        }
    }
    float mb0 = m1b[d0], mb1 = m1b[d1];
    float lb = (s < 6) ? m2b[s] : 0.f;
    float h0 = 0.f, h1 = 0.f;
    int act = AA_ - 1;

    float* outp = out_logits + row * (TSTEPS * 6);

    for (int step = 0; step < TSTEPS; step++) {
        int p = step & 1;
        // ---- gh = h @ Whh^T + bhh : 6 outputs per lane ----
        float acc0 = bhhr[0], acc1 = bhhr[1], acc2 = bhhr[2];
        float acc3 = bhhr[3], acc4 = bhhr[4], acc5 = bhhr[5];
        const float4* hp = (const float4*)(HS + (p * 4 + r) * 68);
        #pragma unroll
        for (int k4 = 0; k4 < 16; k4++) {
            float4 h4 = hp[k4];
            const float4* wq = WQ + k4 * 192;
            float4 v;
            v = wq[oidx[0]]; acc0 += h4.x * v.x + h4.y * v.y + h4.z * v.z + h4.w * v.w;
            v = wq[oidx[1]]; acc1 += h4.x * v.x + h4.y * v.y + h4.z * v.z + h4.w * v.w;
            v = wq[oidx[2]]; acc2 += h4.x * v.x + h4.y * v.y + h4.z * v.z + h4.w * v.w;
            v = wq[oidx[3]]; acc3 += h4.x * v.x + h4.y * v.y + h4.z * v.z + h4.w * v.w;
            v = wq[oidx[4]]; acc4 += h4.x * v.x + h4.y * v.y + h4.z * v.z + h4.w * v.w;
            v = wq[oidx[5]]; acc5 += h4.x * v.x + h4.y * v.y + h4.z * v.z + h4.w * v.w;
        }
        const float* atr = AT + act * 208;
        float rg0 = fsigm(bgx[0] + atr[oidx[0]] + acc0);
        float rg1 = fsigm(bgx[1] + atr[oidx[1]] + acc1);
        float zg0 = fsigm(bgx[2] + atr[oidx[2]] + acc2);
        float zg1 = fsigm(bgx[3] + atr[oidx[3]] + acc3);
        float ng0 = tanhf(bgx[4] + atr[oidx[4]] + rg0 * acc4);
        float ng1 = tanhf(bgx[5] + atr[oidx[5]] + rg1 * acc5);
        float hn0 = (1.f - zg0) * ng0 + zg0 * h0;
        float hn1 = (1.f - zg1) * ng1 + zg1 * h1;
        h0 = hn0; h1 = hn1;

        float* hw = HS + (((p ^ 1) * 4) + r) * 68;
        hw[d0] = hn0; hw[d1] = hn1;
        __syncthreads();

        // ---- mlp1: hid = tanh(h_new @ mlp1^T + b) ----
        float m0 = mb0, m1v = mb1;
        const float4* hq = (const float4*)(HS + (((p ^ 1) * 4) + r) * 68);
        #pragma unroll
        for (int k4 = 0; k4 < 16; k4++) {
            float4 h4 = hq[k4];
            float4 v0 = M1[k4 * 64 + d0];
            float4 v1 = M1[k4 * 64 + d1];
            m0  += h4.x * v0.x + h4.y * v0.y + h4.z * v0.z + h4.w * v0.w;
            m1v += h4.x * v1.x + h4.y * v1.y + h4.z * v1.z + h4.w * v1.w;
        }
        float* hdw = HD + r * 68;
        hdw[d0] = tanhf(m0); hdw[d1] = tanhf(m1v);
        __syncthreads();

        // ---- mlp2 + argmax (redundant per warp; no 3rd barrier) ----
        float lacc = lb;
        const float4* hdq = (const float4*)(HD + r * 68);
        #pragma unroll
        for (int k4 = 0; k4 < 16; k4++) {
            float4 h4 = hdq[k4];
            float4 v = M2[k4 * 8 + s];
            lacc += h4.x * v.x + h4.y * v.y + h4.z * v.z + h4.w * v.w;
        }
        if (w == 0 && s < 6) outp[step * 6 + s] = lacc;

        float bv = (s < 6) ? lacc : -3.0e38f;
        int bi = s;
        #pragma unroll
        for (int d = 4; d < 32; d <<= 1) {   // butterfly over s-bits only
            float ov = __shfl_xor_sync(0xffffffffu, bv, d);
            int   oi = __shfl_xor_sync(0xffffffffu, bi, d);
            if (ov > bv || (ov == bv && oi < bi)) { bv = ov; bi = oi; }
        }
        act = bi;  // first-max tie-break, matching jnp.argmax
    }
}

extern "C" void kernel_launch(void* const* d_in, const int* in_sizes, int n_in,
                              void* d_out, int out_size) {
    const float* s_h    = (const float*)d_in[0];
    const int*   a_h    = (const int*)  d_in[1];
    const float* b_z    = (const float*)d_in[2];
    const float* w1     = (const float*)d_in[3];
    const float* b1     = (const float*)d_in[4];
    const float* w2     = (const float*)d_in[5];
    const float* b2     = (const float*)d_in[6];
    const float* fcw    = (const float*)d_in[7];
    const float* fcb    = (const float*)d_in[8];
    const float* emb    = (const float*)d_in[9];
    const float* wih    = (const float*)d_in[10];
    const float* whh    = (const float*)d_in[11];
    const float* bih    = (const float*)d_in[12];
    const float* bhh    = (const float*)d_in[13];
    const float* m1w    = (const float*)d_in[14];
    const float* m1b    = (const float*)d_in[15];
    const float* m2w    = (const float*)d_in[16];
    const float* m2b    = (const float*)d_in[17];

    float* out = (float*)d_out;
    float* out_logits = out;                       // [B,N,T-1,A] = 487680
    float* out_masks  = out + BN_ * TSTEPS * AA_;  // [B,N,T,1]   = 81920

    // ~74 KB dynamic smem for recur_kernel: opt-in above 48 KB default.
    static const size_t RECUR_SMEM =
        (16 * 192 + 16 * 64 + 16 * 8) * sizeof(float4) +
        (6 * 208 + 2 * 4 * 68 + 4 * 68) * sizeof(float);
    cudaFuncSetAttribute(recur_kernel,
                         cudaFuncAttributeMaxDynamicSharedMemorySize,
                         (int)RECUR_SMEM);

    encoder_kernel<<<BN_, 128>>>(s_h, a_h, w1, b1, w2, b2, fcw, fcb, out_masks);
    recur_kernel<<<160, 128, RECUR_SMEM>>>(b_z, emb, wih, whh, bih, bhh,
                                           m1w, m1b, m2w, m2b, out_logits);
}